// round 13
// baseline (speedup 1.0000x reference)
#include <cuda_runtime.h>
#include <cuda_bf16.h>
#include <cstdint>
#include <cstddef>

// Problem constants
#define T_TOKENS 131072      // 8*128*128
#define C_DIM    320
#define QKV_N    960
#define MLP_N    1280
#define HEADS    32
#define DHEAD    10

// fp8 scaling: A1 = fp8(16*xn), B1 = fp8(16*w1)  -> acc1 = 256*(xn@w1)
//              h_st = fp8(relu(acc1)/4) = fp8(64*h_true)
//              B2 = fp8(16*w2)                   -> acc2 = 1024*(h@w2)
#define H_STORE_SCALE   0.25f
#define MLP2_ACC_SCALE  (1.0f / 1024.0f)
#define W_SCALE         16.0f
#define XN_SCALE        16.0f

// ---------------- scratch (device globals) ------------------------------------
__device__ float          g_xn  [ (size_t)T_TOKENS * C_DIM ];
__device__ __nv_bfloat16  g_xnb [ (size_t)T_TOKENS * C_DIM ];
__device__ uint8_t        g_xnf8[ (size_t)T_TOKENS * C_DIM ];
__device__ float          g_qkv [ (size_t)T_TOKENS * QKV_N ];
__device__ __nv_bfloat16  g_ovb [ (size_t)T_TOKENS * C_DIM ];
__device__ float          g_xa  [ (size_t)T_TOKENS * C_DIM ];
__device__ uint8_t        g_hf8 [ (size_t)T_TOKENS * MLP_N ];
__device__ __nv_bfloat16  g_qwb [ (size_t)C_DIM * QKV_N ];
__device__ __nv_bfloat16  g_pwb [ (size_t)C_DIM * C_DIM ];
__device__ uint8_t        g_w1t8[ (size_t)MLP_N * C_DIM ];   // [N,K] fp8, x16
__device__ uint8_t        g_w2t8[ (size_t)C_DIM * MLP_N ];   // [N,K] fp8, x16

// ---------------- asm helpers --------------------------------------------------
#define CP_ASYNC16(dst_u32, src_ptr) \
    asm volatile("cp.async.cg.shared.global [%0], [%1], 16;\n" :: "r"(dst_u32), "l"(src_ptr))
#define CP_COMMIT() asm volatile("cp.async.commit_group;\n" ::)
#define CP_WAIT(n)  asm volatile("cp.async.wait_group %0;\n" :: "n"(n))

__device__ __forceinline__ uint32_t smem_u32(const void* p) {
    return (uint32_t)__cvta_generic_to_shared(p);
}

#define LDSM_X4(r0,r1,r2,r3,addr) \
    asm volatile("ldmatrix.sync.aligned.m8n8.x4.shared.b16 {%0,%1,%2,%3},[%4];\n" \
        : "=r"(r0),"=r"(r1),"=r"(r2),"=r"(r3) : "r"(addr))
#define LDSM_X4T(r0,r1,r2,r3,addr) \
    asm volatile("ldmatrix.sync.aligned.m8n8.x4.trans.shared.b16 {%0,%1,%2,%3},[%4];\n" \
        : "=r"(r0),"=r"(r1),"=r"(r2),"=r"(r3) : "r"(addr))

#define MMA_BF16(c, a, b) \
    asm volatile("mma.sync.aligned.m16n8k16.row.col.f32.bf16.bf16.f32 " \
        "{%0,%1,%2,%3},{%4,%5,%6,%7},{%8,%9},{%0,%1,%2,%3};\n" \
        : "+f"(c[0]),"+f"(c[1]),"+f"(c[2]),"+f"(c[3]) \
        : "r"(a[0]),"r"(a[1]),"r"(a[2]),"r"(a[3]),"r"(b[0]),"r"(b[1]))

#define MMA_FP8(c, a, b) \
    asm volatile("mma.sync.aligned.m16n8k32.row.col.f32.e4m3.e4m3.f32 " \
        "{%0,%1,%2,%3},{%4,%5,%6,%7},{%8,%9},{%0,%1,%2,%3};\n" \
        : "+f"(c[0]),"+f"(c[1]),"+f"(c[2]),"+f"(c[3]) \
        : "r"(a[0]),"r"(a[1]),"r"(a[2]),"r"(a[3]),"r"(b[0]),"r"(b[1]))

// pack two floats to e4m3x2: low byte = vlo, high byte = vhi
__device__ __forceinline__ uint16_t f2_to_e4m3x2(float vlo, float vhi) {
    uint16_t u;
    asm("cvt.rn.satfinite.e4m3x2.f32 %0, %1, %2;\n" : "=h"(u) : "f"(vhi), "f"(vlo));
    return u;
}

// ---------------- l2 normalize along C=320, one warp per token ----------------
// MODE 0: write f32 + bf16.  MODE 1: write f32 + fp8(16*xn).
template <int MODE>
__global__ __launch_bounds__(256) void l2norm_kernel(const float* __restrict__ in,
                                                     float* __restrict__ out,
                                                     __nv_bfloat16* __restrict__ outb,
                                                     uint8_t* __restrict__ outf8) {
    int row  = blockIdx.x * 8 + (threadIdx.x >> 5);
    int lane = threadIdx.x & 31;
    const float* p = in + (size_t)row * C_DIM;
    float v[10];
    float s = 0.f;
#pragma unroll
    for (int i = 0; i < 10; i++) { v[i] = p[lane + 32 * i]; s += v[i] * v[i]; }
#pragma unroll
    for (int sh = 16; sh; sh >>= 1) s += __shfl_xor_sync(0xffffffffu, s, sh);
    float n = fmaxf(sqrtf(s), 1e-12f);
    float inv = 1.0f / n;
    float* q = out + (size_t)row * C_DIM;
#pragma unroll
    for (int i = 0; i < 10; i++) {
        float o = v[i] * inv;
        q[lane + 32 * i] = o;
        if (MODE == 0) {
            outb[(size_t)row * C_DIM + lane + 32 * i] = __float2bfloat16(o);
        } else {
            float os = o * XN_SCALE;
            float on = __shfl_down_sync(0xffffffffu, os, 1);
            if (!(lane & 1)) {
                uint16_t u = f2_to_e4m3x2(os, on);
                *reinterpret_cast<uint16_t*>(outf8 + (size_t)row * C_DIM + lane + 32 * i) = u;
            }
        }
    }
}

// ---------------- fp32 -> bf16 conversion (weights, [K,N] layout kept) --------
__global__ __launch_bounds__(256) void cvt_bf16_kernel(const float* __restrict__ in,
                                                       __nv_bfloat16* __restrict__ out) {
    int i = (blockIdx.x * 256 + threadIdx.x) * 4;
    float4 v = *reinterpret_cast<const float4*>(in + i);
    __nv_bfloat162 lo = __float22bfloat162_rn(make_float2(v.x, v.y));
    __nv_bfloat162 hi = __float22bfloat162_rn(make_float2(v.z, v.w));
    uint32_t lou, hiu;
    memcpy(&lou, &lo, 4); memcpy(&hiu, &hi, 4);
    *reinterpret_cast<uint2*>(out + i) = make_uint2(lou, hiu);
}

// ---------------- weight transpose: [K,N] f32 -> [N,K] fp8 (x W_SCALE) --------
__global__ __launch_bounds__(256) void transpose_fp8_kernel(const float* __restrict__ in,
                                                            uint8_t* __restrict__ out,
                                                            int K, int N) {
    __shared__ float tile[32][33];
    int n0 = blockIdx.x * 32, k0 = blockIdx.y * 32;
    int tx = threadIdx.x & 31, ty = threadIdx.x >> 5;   // 32 x 8
#pragma unroll
    for (int i = 0; i < 32; i += 8)
        tile[ty + i][tx] = in[(size_t)(k0 + ty + i) * N + n0 + tx];
    __syncthreads();
#pragma unroll
    for (int i = 0; i < 32; i += 8) {
        uint16_t u = f2_to_e4m3x2(tile[tx][ty + i] * W_SCALE, 0.f);
        out[(size_t)(n0 + ty + i) * K + k0 + tx] = (uint8_t)(u & 0xFF);
    }
}

// ---------------- bf16 GEMM: 128x64x32 tile, 3-stage cp.async, 8 warps --------
// EPI 0: out(f32) = acc + bias          (qkv)
// EPI 1: out(f32) = acc + bias + res    (proj -> xa)
template <int EPI>
__global__ __launch_bounds__(256) void gemm_bf16(
    const __nv_bfloat16* __restrict__ A, const __nv_bfloat16* __restrict__ Bw,
    const float* __restrict__ bias, const float* __restrict__ res,
    float* __restrict__ Cout, int M, int N, int K)
{
    __shared__ __nv_bfloat16 As[3][128][40];
    __shared__ __nv_bfloat16 Bs[3][32][72];

    const int tid = threadIdx.x, lane = tid & 31, wid = tid >> 5;
    const int wm = (wid >> 1) * 32, wn = (wid & 1) * 32;
    const int bm = blockIdx.y * 128, bn = blockIdx.x * 64;

    float acc[2][4][4];
#pragma unroll
    for (int i = 0; i < 2; i++)
#pragma unroll
        for (int j = 0; j < 4; j++)
#pragma unroll
            for (int r = 0; r < 4; r++) acc[i][j][r] = 0.f;

    const int ar = tid >> 2, ac = (tid & 3) * 8;
    const int br = tid >> 3, bc = (tid & 7) * 8;

#pragma unroll
    for (int p = 0; p < 2; p++) {
        int k0 = p * 32;
        CP_ASYNC16(smem_u32(&As[p][ar][ac]),      A + (size_t)(bm + ar) * K + k0 + ac);
        CP_ASYNC16(smem_u32(&As[p][ar + 64][ac]), A + (size_t)(bm + ar + 64) * K + k0 + ac);
        CP_ASYNC16(smem_u32(&Bs[p][br][bc]),      Bw + (size_t)(k0 + br) * N + bn + bc);
        CP_COMMIT();
    }

    const int TT = K / 32;
    int s = 0;
    for (int t = 0; t < TT; t++) {
        CP_WAIT(1);
        __syncthreads();

        if (t + 2 < TT) {
            int st = s + 2 >= 3 ? s - 1 : s + 2;
            int k0 = (t + 2) * 32;
            CP_ASYNC16(smem_u32(&As[st][ar][ac]),      A + (size_t)(bm + ar) * K + k0 + ac);
            CP_ASYNC16(smem_u32(&As[st][ar + 64][ac]), A + (size_t)(bm + ar + 64) * K + k0 + ac);
            CP_ASYNC16(smem_u32(&Bs[st][br][bc]),      Bw + (size_t)(k0 + br) * N + bn + bc);
            CP_COMMIT();
        } else {
            CP_COMMIT();
        }

#pragma unroll
        for (int ks = 0; ks < 2; ks++) {
            uint32_t af[2][4], bf[4][2];
#pragma unroll
            for (int mt = 0; mt < 2; mt++) {
                uint32_t addr = smem_u32(&As[s][wm + mt * 16 + (lane & 15)][ks * 16 + (lane >> 4) * 8]);
                LDSM_X4(af[mt][0], af[mt][1], af[mt][2], af[mt][3], addr);
            }
#pragma unroll
            for (int p = 0; p < 2; p++) {
                int row = ks * 16 + ((lane >> 3) & 1) * 8 + (lane & 7);
                int col = wn + p * 16 + (lane >> 4) * 8;
                uint32_t r0, r1, r2, r3;
                uint32_t addr = smem_u32(&Bs[s][row][col]);
                LDSM_X4T(r0, r1, r2, r3, addr);
                bf[p * 2][0] = r0; bf[p * 2][1] = r1;
                bf[p * 2 + 1][0] = r2; bf[p * 2 + 1][1] = r3;
            }
#pragma unroll
            for (int mt = 0; mt < 2; mt++)
#pragma unroll
                for (int nt = 0; nt < 4; nt++)
                    MMA_BF16(acc[mt][nt], af[mt], bf[nt]);
        }
        s = (s + 1 == 3) ? 0 : s + 1;
    }

    const int g = lane >> 2, tg = lane & 3;
#pragma unroll
    for (int mt = 0; mt < 2; mt++) {
#pragma unroll
        for (int nt = 0; nt < 4; nt++) {
            int r0 = bm + wm + mt * 16 + g;
            int c0 = bn + wn + nt * 8 + tg * 2;
#pragma unroll
            for (int half = 0; half < 2; half++) {
                int r = r0 + half * 8;
                float v0 = acc[mt][nt][half * 2 + 0] + bias[c0];
                float v1 = acc[mt][nt][half * 2 + 1] + bias[c0 + 1];
                if (EPI == 1) {
                    float2 rr = *reinterpret_cast<const float2*>(res + (size_t)r * N + c0);
                    v0 += rr.x; v1 += rr.y;
                }
                *reinterpret_cast<float2*>(Cout + (size_t)r * N + c0) = make_float2(v0, v1);
            }
        }
    }
}

// ---------------- fp8 GEMM: 128x64x64 tile, 3-stage cp.async, 8 warps ---------
// A [M,K] fp8 row-major, Bt [N,K] fp8 row-major (both K-contiguous).
// EPI 2: out(fp8) = relu(acc) * H_STORE_SCALE                      (mlp1 -> h)
// EPI 3: out(f32) = res + relu(acc*MLP2_ACC_SCALE + bias) * gamma  (mlp2)
template <int EPI>
__global__ __launch_bounds__(256) void gemm_fp8(
    const uint8_t* __restrict__ A, const uint8_t* __restrict__ Bt,
    const float* __restrict__ bias, const float* __restrict__ res,
    const float* __restrict__ gamma, void* __restrict__ Cout,
    int M, int N, int K)
{
    __shared__ uint8_t As[3][128][80];   // 128 x 64 fp8, pad->80 (16B-aligned rows)
    __shared__ uint8_t Bs[3][64][80];    //  64 x 64 fp8, pad->80

    const int tid = threadIdx.x, lane = tid & 31, wid = tid >> 5;
    const int wm = (wid >> 1) * 32, wn = (wid & 1) * 32;
    const int bm = blockIdx.y * 128, bn = blockIdx.x * 64;

    float acc[2][4][4];
#pragma unroll
    for (int i = 0; i < 2; i++)
#pragma unroll
        for (int j = 0; j < 4; j++)
#pragma unroll
            for (int r = 0; r < 4; r++) acc[i][j][r] = 0.f;

    // A: 128 rows x 64B = 512 chunks (2/thread); B: 64 rows x 64B = 256 chunks (1/thread)
    const int ar = tid >> 2, ac = (tid & 3) * 16;
    const int br = tid >> 2, bc = (tid & 3) * 16;

#pragma unroll
    for (int p = 0; p < 2; p++) {
        int k0 = p * 64;
        CP_ASYNC16(smem_u32(&As[p][ar][ac]),      A + (size_t)(bm + ar) * K + k0 + ac);
        CP_ASYNC16(smem_u32(&As[p][ar + 64][ac]), A + (size_t)(bm + ar + 64) * K + k0 + ac);
        if (tid < 256) CP_ASYNC16(smem_u32(&Bs[p][br][bc]), Bt + (size_t)(bn + br) * K + k0 + bc);
        CP_COMMIT();
    }

    const int TT = K / 64;
    int s = 0;
    for (int t = 0; t < TT; t++) {
        CP_WAIT(1);
        __syncthreads();

        if (t + 2 < TT) {
            int st = s + 2 >= 3 ? s - 1 : s + 2;
            int k0 = (t + 2) * 64;
            CP_ASYNC16(smem_u32(&As[st][ar][ac]),      A + (size_t)(bm + ar) * K + k0 + ac);
            CP_ASYNC16(smem_u32(&As[st][ar + 64][ac]), A + (size_t)(bm + ar + 64) * K + k0 + ac);
            CP_ASYNC16(smem_u32(&Bs[st][br][bc]),      Bt + (size_t)(bn + br) * K + k0 + bc);
            CP_COMMIT();
        } else {
            CP_COMMIT();
        }

#pragma unroll
        for (int ks = 0; ks < 2; ks++) {     // two k32 steps per 64-chunk
            uint32_t af[2][4], bf[4][2];
            // A fragments: m16k32 fp8 via one non-trans LDSM_X4 (b16-unit view)
#pragma unroll
            for (int mt = 0; mt < 2; mt++) {
                uint32_t addr = smem_u32(&As[s][wm + mt * 16 + (lane & 15)][ks * 32 + (lane >> 4) * 16]);
                LDSM_X4(af[mt][0], af[mt][1], af[mt][2], af[mt][3], addr);
            }
            // B fragments: 4 x (n8,k32) via 2 non-trans LDSM_X4 on [N,K] tiles
#pragma unroll
            for (int p = 0; p < 2; p++) {
                int row = wn + p * 16 + ((lane >> 3) & 1) * 8 + (lane & 7);
                int col = ks * 32 + (lane >> 4) * 16;
                uint32_t r0, r1, r2, r3;
                uint32_t addr = smem_u32(&Bs[s][row][col]);
                LDSM_X4(r0, r1, r2, r3, addr);
                // m0=(n0-7,k0-15)=b0 g0, m1=(n8-15,k0-15)=b0 g1,
                // m2=(n0-7,k16-31)=b1 g0, m3=(n8-15,k16-31)=b1 g1
                bf[p * 2][0] = r0;     bf[p * 2][1] = r2;
                bf[p * 2 + 1][0] = r1; bf[p * 2 + 1][1] = r3;
            }
#pragma unroll
            for (int mt = 0; mt < 2; mt++)
#pragma unroll
                for (int nt = 0; nt < 4; nt++)
                    MMA_FP8(acc[mt][nt], af[mt], bf[nt]);
        }
        s = (s + 1 == 3) ? 0 : s + 1;
    }

    const int g = lane >> 2, tg = lane & 3;
#pragma unroll
    for (int mt = 0; mt < 2; mt++) {
#pragma unroll
        for (int nt = 0; nt < 4; nt++) {
            int r0 = bm + wm + mt * 16 + g;
            int c0 = bn + wn + nt * 8 + tg * 2;
#pragma unroll
            for (int half = 0; half < 2; half++) {
                int r = r0 + half * 8;
                float v0 = acc[mt][nt][half * 2 + 0];
                float v1 = acc[mt][nt][half * 2 + 1];
                if (EPI == 2) {
                    v0 = fmaxf(v0, 0.f) * H_STORE_SCALE;
                    v1 = fmaxf(v1, 0.f) * H_STORE_SCALE;
                    uint16_t u = f2_to_e4m3x2(v0, v1);
                    *reinterpret_cast<uint16_t*>((uint8_t*)Cout + (size_t)r * N + c0) = u;
                } else { // EPI == 3
                    float2 rr = *reinterpret_cast<const float2*>(res + (size_t)r * N + c0);
                    float o0 = rr.x + fmaxf(v0 * MLP2_ACC_SCALE + bias[c0], 0.f) * gamma[c0];
                    float o1 = rr.y + fmaxf(v1 * MLP2_ACC_SCALE + bias[c0 + 1], 0.f) * gamma[c0 + 1];
                    *reinterpret_cast<float2*>((float*)Cout + (size_t)r * N + c0) = make_float2(o0, o1);
                }
            }
        }
    }
}

// ---------------- window attention, flash-style, bf16 out ---------------------
__global__ __launch_bounds__(256) void attn_kernel(const float* __restrict__ qkv,
                                                   __nv_bfloat16* __restrict__ o) {
    const int w   = blockIdx.y;
    const int hg  = blockIdx.x;
    const int b   = w >> 8, rem = w & 255;
    const int wh  = rem >> 4, ww = rem & 15;
    const int tid = threadIdx.x, lane = tid & 31, warp = tid >> 5;
    const int head = hg * 8 + warp;

    __shared__ float ks[8][64][10];
    __shared__ float vs[8][64][10];

    const int base_tok = (b * 128 + wh * 8) * 128 + ww * 8;

    for (int idx = tid; idx < 64 * 8 * 20; idx += 256) {
        int n  = idx / 160;
        int c  = idx - n * 160;
        int h2 = c / 20;
        int cc = c - h2 * 20;
        int tok = base_tok + (n >> 3) * 128 + (n & 7);
        float v = qkv[(size_t)tok * QKV_N + (hg * 8 + h2) * 30 + 10 + cc];
        if (cc < 10) ks[h2][n][cc] = v;
        else         vs[h2][n][cc - 10] = v;
    }
    __syncthreads();

    const float scale = 0.31622776601683794f;
    float q[2][10], acc[2][10];
    float mx[2] = {-1e30f, -1e30f}, l[2] = {0.f, 0.f};
    int toks[2];
#pragma unroll
    for (int p = 0; p < 2; p++) {
        int r = lane + p * 32;
        int tok = base_tok + (r >> 3) * 128 + (r & 7);
        toks[p] = tok;
        const float* qp = qkv + (size_t)tok * QKV_N + head * 30;
#pragma unroll
        for (int d = 0; d < 10; d++) { q[p][d] = qp[d]; acc[p][d] = 0.f; }
    }

    for (int m = 0; m < 64; m++) {
        float kv[10];
#pragma unroll
        for (int d = 0; d < 10; d++) kv[d] = ks[warp][m][d];
#pragma unroll
        for (int p = 0; p < 2; p++) {
            float s = 0.f;
#pragma unroll
            for (int d = 0; d < 10; d++) s += q[p][d] * kv[d];
            s *= scale;
            if (s > mx[p]) {
                float c = __expf(mx[p] - s);
                l[p] *= c;
#pragma unroll
                for (int d = 0; d < 10; d++) acc[p][d] *= c;
                mx[p] = s;
            }
            float e = __expf(s - mx[p]);
            l[p] += e;
#pragma unroll
            for (int d = 0; d < 10; d++) acc[p][d] += e * vs[warp][m][d];
        }
    }

#pragma unroll
    for (int p = 0; p < 2; p++) {
        float inv = 1.0f / l[p];
        uint32_t* op = reinterpret_cast<uint32_t*>(o + (size_t)toks[p] * C_DIM + head * DHEAD);
#pragma unroll
        for (int d = 0; d < 5; d++) {
            __nv_bfloat162 pk = __float22bfloat162_rn(
                make_float2(acc[p][2 * d] * inv, acc[p][2 * d + 1] * inv));
            uint32_t pku; memcpy(&pku, &pk, 4);
            op[d] = pku;
        }
    }
}

// ---------------- launch ------------------------------------------------------
extern "C" void kernel_launch(void* const* d_in, const int* in_sizes, int n_in,
                              void* d_out, int out_size) {
    const float* x      = (const float*)d_in[0];
    const float* qkv_w  = (const float*)d_in[1];
    const float* qkv_b  = (const float*)d_in[2];
    const float* proj_w = (const float*)d_in[3];
    const float* proj_b = (const float*)d_in[4];
    const float* gamma  = (const float*)d_in[5];
    const float* w1     = (const float*)d_in[6];
    const float* w2     = (const float*)d_in[7];
    const float* b2     = (const float*)d_in[8];
    float* out = (float*)d_out;

    float *xn, *qkv, *xa;
    __nv_bfloat16 *xnb, *ovb, *qwb, *pwb;
    uint8_t *xnf8, *hf8, *w1t8, *w2t8;
    cudaGetSymbolAddress((void**)&xn,   g_xn);
    cudaGetSymbolAddress((void**)&xnb,  g_xnb);
    cudaGetSymbolAddress((void**)&xnf8, g_xnf8);
    cudaGetSymbolAddress((void**)&qkv,  g_qkv);
    cudaGetSymbolAddress((void**)&ovb,  g_ovb);
    cudaGetSymbolAddress((void**)&xa,   g_xa);
    cudaGetSymbolAddress((void**)&hf8,  g_hf8);
    cudaGetSymbolAddress((void**)&qwb,  g_qwb);
    cudaGetSymbolAddress((void**)&pwb,  g_pwb);
    cudaGetSymbolAddress((void**)&w1t8, g_w1t8);
    cudaGetSymbolAddress((void**)&w2t8, g_w2t8);

    const int M = T_TOKENS;
    dim3 blk(256);

    // weight preps
    cvt_bf16_kernel<<<300, blk>>>(qkv_w, qwb);                                    // 320x960 bf16
    cvt_bf16_kernel<<<100, blk>>>(proj_w, pwb);                                   // 320x320 bf16
    transpose_fp8_kernel<<<dim3(MLP_N / 32, C_DIM / 32), blk>>>(w1, w1t8, C_DIM, MLP_N);
    transpose_fp8_kernel<<<dim3(C_DIM / 32, MLP_N / 32), blk>>>(w2, w2t8, MLP_N, C_DIM);

    // 1. xn,xnb = l2norm(x)
    l2norm_kernel<0><<<M / 8, blk>>>(x, xn, xnb, nullptr);

    // 2. qkv = xnb @ qkv_w + qkv_b   (bf16)
    gemm_bf16<0><<<dim3(QKV_N / 64, M / 128), blk>>>(xnb, qwb, qkv_b, nullptr, qkv, M, QKV_N, C_DIM);

    // 3. windowed attention -> ovb (bf16)
    attn_kernel<<<dim3(4, 2048), blk>>>(qkv, ovb);

    // 4. xa = xn + ovb @ proj_w + proj_b   (bf16)
    gemm_bf16<1><<<dim3(C_DIM / 64, M / 128), blk>>>(ovb, pwb, proj_b, xn, xa, M, C_DIM, C_DIM);

    // 5. xn,xnf8 = l2norm(xa)
    l2norm_kernel<1><<<M / 8, blk>>>(xa, xn, nullptr, xnf8);

    // 6. h = relu(xnf8 @ w1) (fp8 in/out, scaled)
    gemm_fp8<2><<<dim3(MLP_N / 64, M / 128), blk>>>(xnf8, w1t8, nullptr, nullptr, nullptr, hf8, M, MLP_N, C_DIM);

    // 7. out = xn + relu(h @ w2 + b2) * gamma   (fp8 in, f32 out)
    gemm_fp8<3><<<dim3(C_DIM / 64, M / 128), blk>>>(hf8, w2t8, b2, xn, gamma, out, M, C_DIM, MLP_N);
}